// round 1
// baseline (speedup 1.0000x reference)
#include <cuda_runtime.h>
#include <math.h>

// Problem constants (fixed by reference setup_inputs)
#define BATCH   32
#define LAYERS  32
#define DIM     4096
#define SELK    24
#define NCHOICE 9        // LAYERS - SELK + 1
#define GS_EPS  1e-10f

// out layout (tuple flatten order):
//   [0, BATCH*SELK*DIM)                    selected_features  (B, K, D) fp32
//   [BATCH*SELK*DIM, +BATCH*NCHOICE)       selection_probs    (B, C)    fp32
//
// selection_probs forward value == one-hot(argmax(logits + gumbel(noise)))
// selected_features[b,k,:] == all_features[b, idx[b]+k, :]  (contiguous span)

__global__ void layer_selector_kernel(const float* __restrict__ feats,
                                      const float* __restrict__ logits,
                                      const float* __restrict__ noise,
                                      float* __restrict__ out) {
    const int b = blockIdx.y;

    __shared__ int s_idx;
    if (threadIdx.x == 0) {
        // Gumbel-perturbed argmax for this batch. 9 choices, first-max wins
        // (strict > while scanning forward == jnp.argmax tie semantics).
        float best = -INFINITY;
        int   bi   = 0;
        #pragma unroll
        for (int c = 0; c < NCHOICE; c++) {
            float u = noise[b * NCHOICE + c];
            float g = -logf(-logf(u + GS_EPS) + GS_EPS);
            float v = logits[c] + g;   // tau = 1; softmax is monotone -> same argmax
            if (v > best) { best = v; bi = c; }
        }
        s_idx = bi;
    }
    __syncthreads();
    const int idx = s_idx;

    // One block per batch writes the one-hot selection_probs tail.
    if (blockIdx.x == 0 && threadIdx.x < NCHOICE) {
        out[(size_t)BATCH * SELK * DIM + b * NCHOICE + threadIdx.x] =
            (threadIdx.x == idx) ? 1.0f : 0.0f;
    }

    // Vectorized contiguous copy: 24*4096 floats = 24576 float4 per batch.
    // grid.x = 96 blocks * 256 threads * 1 float4 covers it exactly.
    const float4* __restrict__ src =
        (const float4*)(feats + (size_t)b * LAYERS * DIM + (size_t)idx * DIM);
    float4* __restrict__ dst = (float4*)(out + (size_t)b * SELK * DIM);

    const int i = blockIdx.x * blockDim.x + threadIdx.x;   // 0 .. 24575
    dst[i] = src[i];
}

extern "C" void kernel_launch(void* const* d_in, const int* in_sizes, int n_in,
                              void* d_out, int out_size) {
    const float* feats  = (const float*)d_in[0];   // all_features (B, L, D)
    const float* logits = (const float*)d_in[1];   // (NCHOICE,)
    const float* noise  = (const float*)d_in[2];   // (B, NCHOICE)
    float*       out    = (float*)d_out;

    // 24576 float4 per batch / 256 threads = 96 blocks per batch
    dim3 grid(96, BATCH);
    dim3 block(256);
    layer_selector_kernel<<<grid, block>>>(feats, logits, noise, out);
}